// round 1
// baseline (speedup 1.0000x reference)
#include <cuda_runtime.h>

#define BB   4
#define NHH  8
#define NN   1024      // H*W
#define MM   21
#define CC   32
#define HD   4
#define DD   84        // M*HD
#define BTOT 4096      // BB*NN
#define NROWS (BTOT*MM)  // 86016 rows of the (B_, M, C) matrix

// ---------------- device scratch (no allocations allowed) ----------------
__device__ float g_q[BB*NHH*NN*DD];
__device__ float g_k[BB*NHH*NN*DD];
__device__ float g_v[BB*NHH*NN*DD];
__device__ float g_x2[BB*NHH*NN];
__device__ float g_pool[BB*NHH];
__device__ float g_xw[NHH*NN];
__device__ float g_xp[NHH*NN];
__device__ float g_tb[NHH*63*63];
__device__ float g_ctx[NROWS*CC];

// ---------------- kernel A: qkv projection + scatter to (b,h,n,d) --------
__global__ void __launch_bounds__(256) qkv_kernel(const float* __restrict__ x,
                                                  const float* __restrict__ W,
                                                  const float* __restrict__ bias) {
    __shared__ float Ws[32*96];
    __shared__ float xs[64][32];
    int t = threadIdx.x;
    for (int i = t; i < 32*96; i += 256) Ws[i] = W[i];
    long rowbase = (long)blockIdx.x * 64;
    for (int i = t; i < 64*32; i += 256) {
        int r = i >> 5, c = i & 31;
        xs[r][c] = x[(rowbase + r)*32 + c];
    }
    __syncthreads();
    int ry = t >> 4, cx = t & 15;   // 16 row-groups x 16 col-groups
    float acc[4][6];
#pragma unroll
    for (int u = 0; u < 4; u++)
#pragma unroll
        for (int v = 0; v < 6; v++) acc[u][v] = 0.f;
#pragma unroll
    for (int kk = 0; kk < 32; kk++) {
        float xv[4], wv[6];
#pragma unroll
        for (int u = 0; u < 4; u++) xv[u] = xs[ry*4+u][kk];
#pragma unroll
        for (int v = 0; v < 6; v++) wv[v] = Ws[kk*96 + cx*6 + v];
#pragma unroll
        for (int u = 0; u < 4; u++)
#pragma unroll
            for (int v = 0; v < 6; v++) acc[u][v] += xv[u]*wv[v];
    }
#pragma unroll
    for (int u = 0; u < 4; u++) {
        long grow = rowbase + ry*4 + u;     // = b_*21 + m
        int b_ = (int)(grow / 21), m = (int)(grow % 21);
        int b = b_ >> 10, n = b_ & 1023;
#pragma unroll
        for (int v = 0; v < 6; v++) {
            int c3 = cx*6 + v;
            float val = acc[u][v] + bias[c3];
            int which = c3 >> 5, h = (c3 >> 2) & 7, d = c3 & 3;
            long dst = (((long)(b*NHH + h))*NN + n)*DD + m*HD + d;
            if (which == 0)      g_q[dst] = val * 0.03125f;  // scale = N^-0.5
            else if (which == 1) g_k[dst] = val;
            else                 g_v[dst] = val;
        }
    }
}

// ---------------- kernel B1: x2 = x-rearranged @ W_sq + b_sq -------------
__global__ void x2_kernel(const float* __restrict__ x,
                          const float* __restrict__ Wsq,
                          const float* __restrict__ bsq) {
    int idx = blockIdx.x*256 + threadIdx.x;       // 32768 = B*nh*N
    int n = idx & 1023, h = (idx >> 10) & 7, b = idx >> 13;
    const float* xr = x + ((long)(b*NN + n))*MM*CC + h*HD;
    float acc = bsq[0];
#pragma unroll
    for (int m = 0; m < MM; m++)
#pragma unroll
        for (int d = 0; d < HD; d++)
            acc += xr[m*CC + d] * Wsq[m*HD + d];
    g_x2[idx] = acc;
}

// ---------------- kernel B2: per-(b,h) avg+max pooling --------------------
__global__ void pool_kernel() {
    int bh = blockIdx.x, t = threadIdx.x;
    const float* p = g_x2 + bh*NN;
    float s = 0.f, mx = -1e30f;
    for (int i = t; i < NN; i += 256) { float v = p[i]; s += v; mx = fmaxf(mx, v); }
    __shared__ float ss[256], sm_[256];
    ss[t] = s; sm_[t] = mx;
    __syncthreads();
    for (int o = 128; o > 0; o >>= 1) {
        if (t < o) { ss[t] += ss[t+o]; sm_[t] = fmaxf(sm_[t], sm_[t+o]); }
        __syncthreads();
    }
    if (t == 0) g_pool[bh] = ss[0]*(1.f/1024.f) + sm_[0];
}

// ---------------- kernel B3: depthwise conv + pooled, mean over batch ----
__global__ void conv_kernel(const float* __restrict__ Wdw,
                            const float* __restrict__ bdw) {
    int idx = blockIdx.x*256 + threadIdx.x;       // 16384 = 16 * 1024
    int pos = idx & 1023, o = idx >> 10;
    int y = pos >> 5, xx = pos & 31;
    int ic = o >> 1;                               // group = o/2 (2 out per group)
    float acc = 0.f;
    for (int b = 0; b < BB; b++) {
        const float* src = g_x2 + (b*NHH + ic)*NN;
        float c = bdw[o] + g_pool[b*NHH + (o & 7)];
#pragma unroll
        for (int ky = 0; ky < 3; ky++) {
            int yy = y + ky - 1; if (yy < 0 || yy >= 32) continue;
#pragma unroll
            for (int kx = 0; kx < 3; kx++) {
                int x2i = xx + kx - 1; if (x2i < 0 || x2i >= 32) continue;
                c += src[yy*32 + x2i] * Wdw[o*9 + ky*3 + kx];
            }
        }
        acc += c;
    }
    acc *= 0.25f;
    if (o < 8) g_xw[o*NN + pos] = acc;
    else       g_xp[(o-8)*NN + pos] = acc;
}

// ---------------- kernel B4: full conv -> 63x63 bias table per head ------
__global__ void table_kernel() {
    int h = blockIdx.y, t = threadIdx.x;
    __shared__ float xw[1024], xp[1024];
    for (int i = t; i < 1024; i += 256) { xw[i] = g_xw[h*NN + i]; xp[i] = g_xp[h*NN + i]; }
    __syncthreads();
    int pq = blockIdx.x*256 + t;
    if (pq < 63*63) {
        int p = pq / 63, q = pq % 63;
        float acc = 0.f;
        int alo = max(0, p-31), ahi = min(31, p);
        int blo = max(0, q-31), bhi = min(31, q);
        for (int a = alo; a <= ahi; a++)
            for (int b2 = blo; b2 <= bhi; b2++)
                acc += xw[a*32 + b2] * xp[(p-a)*32 + (q-b2)];
        g_tb[h*3969 + pq] = acc;
    }
}

// ---------------- kernel C: fused flash attention with bias --------------
#define BM 128
#define BN 64
#define QP 132
#define KP 68
#define VP 96
#define QT_OFF 0
#define KT_OFF (84*132)            // 11088
#define V_OFF  (KT_OFF + 84*68)    // 16800
#define P_OFF  (V_OFF + 64*96)     // 22944
#define TB_OFF (P_OFF + 128*64)    // 31136
#define SMEM_FLOATS (TB_OFF + 3969)  // 35105 floats = 140420 B

__global__ void __launch_bounds__(256) flash_kernel() {
    extern __shared__ float smf[];
    float* Qt = smf + QT_OFF;
    float* Kt = smf + KT_OFF;
    float* Vs = smf + V_OFF;
    float* Ps = smf + P_OFF;
    float* TB = smf + TB_OFF;

    int t = threadIdx.x;
    int tx = t & 15, ty = t >> 4;
    int qt = blockIdx.x;          // 0..7
    int bh = blockIdx.y;          // 0..31 = b*8 + h
    int h = bh & 7;
    int b = bh >> 3;
    const float* qp = g_q + (long)bh*NN*DD;
    const float* kp = g_k + (long)bh*NN*DD;
    const float* vp = g_v + (long)bh*NN*DD;

    for (int i = t; i < 3969; i += 256) TB[i] = g_tb[h*3969 + i];
    int q0 = qt*BM;
    for (int i = t; i < BM*DD; i += 256) {
        int r = i / 84, d = i % 84;
        Qt[d*QP + r] = qp[(q0 + r)*DD + d];
    }

    float mrow[8], lrow[8], acc[8][6];
#pragma unroll
    for (int i = 0; i < 8; i++) {
        mrow[i] = -1e30f; lrow[i] = 0.f;
#pragma unroll
        for (int j = 0; j < 6; j++) acc[i][j] = 0.f;
    }

    for (int kt = 0; kt < 16; kt++) {
        __syncthreads();   // protects Kt/Vs/Ps reuse + first-iter Qt/TB
        int k0 = kt*BN;
        for (int i = t; i < BN*DD; i += 256) {
            int c = i / 84, d = i % 84;
            Kt[d*KP + c] = kp[(k0 + c)*DD + d];
        }
        for (int i = t; i < BN*VP; i += 256) {
            int c = i / 96, d = i % 96;
            Vs[i] = (d < 84) ? vp[(k0 + c)*DD + d] : 0.f;
        }
        __syncthreads();

        // ---- S = Q @ K^T (128x64), thread tile 8x4 ----
        float s[8][4];
#pragma unroll
        for (int i = 0; i < 8; i++)
#pragma unroll
            for (int j = 0; j < 4; j++) s[i][j] = 0.f;

#pragma unroll 2
        for (int dd = 0; dd < 84; dd++) {
            float4 kk4 = *(const float4*)(Kt + dd*KP + tx*4);
            float4 qa  = *(const float4*)(Qt + dd*QP + ty*8);
            float4 qb  = *(const float4*)(Qt + dd*QP + ty*8 + 4);
            float q8[8] = {qa.x, qa.y, qa.z, qa.w, qb.x, qb.y, qb.z, qb.w};
            float k4[4] = {kk4.x, kk4.y, kk4.z, kk4.w};
#pragma unroll
            for (int i = 0; i < 8; i++)
#pragma unroll
                for (int j = 0; j < 4; j++) s[i][j] += q8[i]*k4[j];
        }

        // ---- bias + online softmax ----
        int i2[4], j2[4];
#pragma unroll
        for (int j = 0; j < 4; j++) {
            int n2 = k0 + tx*4 + j;
            i2[j] = n2 >> 5; j2[j] = n2 & 31;
        }
#pragma unroll
        for (int i = 0; i < 8; i++) {
            int n1 = q0 + ty*8 + i;
            int i1 = n1 >> 5, j1 = n1 & 31;
            float rmax = -1e30f;
#pragma unroll
            for (int j = 0; j < 4; j++) {
                s[i][j] += TB[(i1 - i2[j] + 31)*63 + (j1 - j2[j] + 31)];
                rmax = fmaxf(rmax, s[i][j]);
            }
#pragma unroll
            for (int off = 8; off; off >>= 1)
                rmax = fmaxf(rmax, __shfl_xor_sync(0xffffffffu, rmax, off));
            float mnew = fmaxf(mrow[i], rmax);
            float alpha = __expf(mrow[i] - mnew);
            mrow[i] = mnew;
            lrow[i] *= alpha;
#pragma unroll
            for (int j = 0; j < 6; j++) acc[i][j] *= alpha;
            float rsum = 0.f;
#pragma unroll
            for (int j = 0; j < 4; j++) {
                float pv = __expf(s[i][j] - mnew);
                s[i][j] = pv; rsum += pv;
            }
#pragma unroll
            for (int off = 8; off; off >>= 1)
                rsum += __shfl_xor_sync(0xffffffffu, rsum, off);
            lrow[i] += rsum;
            float4 p4 = make_float4(s[i][0], s[i][1], s[i][2], s[i][3]);
            *(float4*)(Ps + (ty*8 + i)*64 + tx*4) = p4;
        }
        __syncthreads();

        // ---- O += P @ V, thread owns rows ty*8..+7, cols d = tx + 16*j ----
#pragma unroll 2
        for (int c = 0; c < 64; c++) {
            float vv[6];
#pragma unroll
            for (int j = 0; j < 6; j++) vv[j] = Vs[c*VP + tx + 16*j];
#pragma unroll
            for (int i = 0; i < 8; i++) {
                float pv = Ps[(ty*8 + i)*64 + c];
#pragma unroll
                for (int j = 0; j < 6; j++) acc[i][j] += pv*vv[j];
            }
        }
    }

    // ---- epilogue: normalize, scatter to (B_, M, C) context layout ----
#pragma unroll
    for (int i = 0; i < 8; i++) {
        int n1 = q0 + ty*8 + i;
        float inv = 1.f / lrow[i];
        long base = ((long)(b*NN + n1)*MM)*CC + h*HD;
#pragma unroll
        for (int j = 0; j < 6; j++) {
            int d84 = tx + 16*j;
            if (d84 < 84) {
                int m = d84 >> 2, d = d84 & 3;
                g_ctx[base + m*CC + d] = acc[i][j]*inv;
            }
        }
    }
}

// ---------------- kernel D: output projection ----------------------------
__global__ void __launch_bounds__(256) proj_kernel(const float* __restrict__ W,
                                                   const float* __restrict__ bias,
                                                   float* __restrict__ out) {
    __shared__ float Ws[32*32];
    __shared__ float xs[64][32];
    int t = threadIdx.x;
    for (int i = t; i < 1024; i += 256) Ws[i] = W[i];
    long rowbase = (long)blockIdx.x * 64;
    for (int i = t; i < 64*32; i += 256) {
        int r = i >> 5, c = i & 31;
        xs[r][c] = g_ctx[(rowbase + r)*32 + c];
    }
    __syncthreads();
    int ry = t >> 4, cx = t & 15;
    float acc[4][2] = {};
#pragma unroll
    for (int kk = 0; kk < 32; kk++) {
        float xv[4], wv[2];
#pragma unroll
        for (int u = 0; u < 4; u++) xv[u] = xs[ry*4+u][kk];
        wv[0] = Ws[kk*32 + cx*2];
        wv[1] = Ws[kk*32 + cx*2 + 1];
#pragma unroll
        for (int u = 0; u < 4; u++) { acc[u][0] += xv[u]*wv[0]; acc[u][1] += xv[u]*wv[1]; }
    }
#pragma unroll
    for (int u = 0; u < 4; u++)
#pragma unroll
        for (int v = 0; v < 2; v++)
            out[(rowbase + ry*4 + u)*32 + cx*2 + v] = acc[u][v] + bias[cx*2 + v];
}

// ---------------- launch ---------------------------------------------------
extern "C" void kernel_launch(void* const* d_in, const int* in_sizes, int n_in,
                              void* d_out, int out_size) {
    (void)in_sizes; (void)n_in; (void)out_size;
    const float* x     = (const float*)d_in[0];
    const float* Wqkv  = (const float*)d_in[1];
    const float* bqkv  = (const float*)d_in[2];
    const float* Wproj = (const float*)d_in[3];
    const float* bproj = (const float*)d_in[4];
    const float* Wsq   = (const float*)d_in[5];
    const float* bsq   = (const float*)d_in[6];
    const float* Wdw   = (const float*)d_in[7];
    const float* bdw   = (const float*)d_in[8];
    float* out = (float*)d_out;

    cudaFuncSetAttribute(flash_kernel,
                         cudaFuncAttributeMaxDynamicSharedMemorySize,
                         SMEM_FLOATS * (int)sizeof(float));

    qkv_kernel  <<<NROWS/64, 256>>>(x, Wqkv, bqkv);
    x2_kernel   <<<(BB*NHH*NN)/256, 256>>>(x, Wsq, bsq);
    pool_kernel <<<BB*NHH, 256>>>();
    conv_kernel <<<(2*NHH*NN)/256, 256>>>(Wdw, bdw);
    table_kernel<<<dim3(16, NHH), 256>>>();
    flash_kernel<<<dim3(NN/BM, BB*NHH), 256, SMEM_FLOATS*sizeof(float)>>>();
    proj_kernel <<<NROWS/64, 256>>>(Wproj, bproj, out);
}

// round 7
// speedup vs baseline: 1.8306x; 1.8306x over previous
#include <cuda_runtime.h>
#include <cstdint>

#define BB   4
#define NHH  8
#define NN   1024
#define MM   21
#define CC   32
#define HD   4
#define DD   84
#define NROWS (BB*NN*MM)

// ---------------- device scratch ----------------
__device__ float g_q[BB*NHH*NN*DD];
__device__ float g_k[BB*NHH*NN*DD];
__device__ float g_vt[BB*NHH*96*NN];     // transposed V: rows d (84 used), cols key
__device__ float g_x2[BB*NHH*NN];
__device__ float g_pool[BB*NHH];
__device__ float g_xw[NHH*NN];
__device__ float g_xp[NHH*NN];
__device__ float g_tb[NHH*63*63];
__device__ float g_rowmax[NHH*NN];
__device__ float g_ctx[NROWS*CC];

// ---------------- kernel A: qkv projection + scatter --------
__global__ void __launch_bounds__(256) qkv_kernel(const float* __restrict__ x,
                                                  const float* __restrict__ W,
                                                  const float* __restrict__ bias) {
    __shared__ float Ws[32*96];
    __shared__ float xs[64][32];
    int t = threadIdx.x;
    for (int i = t; i < 32*96; i += 256) Ws[i] = W[i];
    long rowbase = (long)blockIdx.x * 64;
    for (int i = t; i < 64*32; i += 256) {
        int r = i >> 5, c = i & 31;
        xs[r][c] = x[(rowbase + r)*32 + c];
    }
    __syncthreads();
    int ry = t >> 4, cx = t & 15;
    float acc[4][6];
#pragma unroll
    for (int u = 0; u < 4; u++)
#pragma unroll
        for (int v = 0; v < 6; v++) acc[u][v] = 0.f;
#pragma unroll
    for (int kk = 0; kk < 32; kk++) {
        float xv[4], wv[6];
#pragma unroll
        for (int u = 0; u < 4; u++) xv[u] = xs[ry*4+u][kk];
#pragma unroll
        for (int v = 0; v < 6; v++) wv[v] = Ws[kk*96 + cx*6 + v];
#pragma unroll
        for (int u = 0; u < 4; u++)
#pragma unroll
            for (int v = 0; v < 6; v++) acc[u][v] += xv[u]*wv[v];
    }
#pragma unroll
    for (int u = 0; u < 4; u++) {
        long grow = rowbase + ry*4 + u;
        int b_ = (int)(grow / 21), m = (int)(grow % 21);
        int b = b_ >> 10, n = b_ & 1023;
#pragma unroll
        for (int v = 0; v < 6; v++) {
            int c3 = cx*6 + v;
            float val = acc[u][v] + bias[c3];
            int which = c3 >> 5, h = (c3 >> 2) & 7, d = c3 & 3;
            int bh = b*NHH + h, d84 = m*4 + d;
            if (which == 0)
                g_q[(((long)bh)*NN + n)*DD + d84] = val * 0.03125f;
            else if (which == 1)
                g_k[(((long)bh)*NN + n)*DD + d84] = val;
            else
                g_vt[((long)bh*96 + d84)*NN + n] = val;
        }
    }
}

// ---------------- LSPE small kernels ----------------
__global__ void x2_kernel(const float* __restrict__ x,
                          const float* __restrict__ Wsq,
                          const float* __restrict__ bsq) {
    int idx = blockIdx.x*256 + threadIdx.x;
    int n = idx & 1023, h = (idx >> 10) & 7, b = idx >> 13;
    const float* xr = x + ((long)(b*NN + n))*MM*CC + h*HD;
    float acc = bsq[0];
#pragma unroll
    for (int m = 0; m < MM; m++)
#pragma unroll
        for (int d = 0; d < HD; d++)
            acc += xr[m*CC + d] * Wsq[m*HD + d];
    g_x2[idx] = acc;
}

__global__ void pool_kernel() {
    int bh = blockIdx.x, t = threadIdx.x;
    const float* p = g_x2 + bh*NN;
    float s = 0.f, mx = -1e30f;
    for (int i = t; i < NN; i += 256) { float v = p[i]; s += v; mx = fmaxf(mx, v); }
    __shared__ float ss[256], sm_[256];
    ss[t] = s; sm_[t] = mx;
    __syncthreads();
    for (int o = 128; o > 0; o >>= 1) {
        if (t < o) { ss[t] += ss[t+o]; sm_[t] = fmaxf(sm_[t], sm_[t+o]); }
        __syncthreads();
    }
    if (t == 0) g_pool[bh] = ss[0]*(1.f/1024.f) + sm_[0];
}

__global__ void conv_kernel(const float* __restrict__ Wdw,
                            const float* __restrict__ bdw) {
    int idx = blockIdx.x*256 + threadIdx.x;
    int pos = idx & 1023, o = idx >> 10;
    int y = pos >> 5, xx = pos & 31;
    int ic = o >> 1;
    float acc = 0.f;
    for (int b = 0; b < BB; b++) {
        const float* src = g_x2 + (b*NHH + ic)*NN;
        float c = bdw[o] + g_pool[b*NHH + (o & 7)];
#pragma unroll
        for (int ky = 0; ky < 3; ky++) {
            int yy = y + ky - 1; if (yy < 0 || yy >= 32) continue;
#pragma unroll
            for (int kx = 0; kx < 3; kx++) {
                int x2i = xx + kx - 1; if (x2i < 0 || x2i >= 32) continue;
                c += src[yy*32 + x2i] * Wdw[o*9 + ky*3 + kx];
            }
        }
        acc += c;
    }
    acc *= 0.25f;
    if (o < 8) g_xw[o*NN + pos] = acc;
    else       g_xp[(o-8)*NN + pos] = acc;
}

__global__ void table_kernel() {
    int h = blockIdx.y, t = threadIdx.x;
    __shared__ float xw[1024], xp[1024];
    for (int i = t; i < 1024; i += 256) { xw[i] = g_xw[h*NN + i]; xp[i] = g_xp[h*NN + i]; }
    __syncthreads();
    int pq = blockIdx.x*256 + t;
    if (pq < 63*63) {
        int p = pq / 63, q = pq % 63;
        float acc = 0.f;
        int alo = max(0, p-31), ahi = min(31, p);
        int blo = max(0, q-31), bhi = min(31, q);
        for (int a = alo; a <= ahi; a++)
            for (int b2 = blo; b2 <= bhi; b2++)
                acc += xw[a*32 + b2] * xp[(p-a)*32 + (q-b2)];
        g_tb[h*3969 + pq] = acc;
    }
}

// per-(h,row) bias max over all 1024 columns (= 32x32 table window)
__global__ void rowmax_kernel() {
    int h = blockIdx.x, t = threadIdx.x;
    __shared__ float tb[3969];
    for (int i = t; i < 3969; i += 256) tb[i] = g_tb[h*3969 + i];
    __syncthreads();
    for (int n1 = t; n1 < 1024; n1 += 256) {
        int i1 = n1 >> 5, j1 = n1 & 31;
        float m = -1e30f;
        for (int a = 0; a < 32; a++)
#pragma unroll 4
            for (int bq = 0; bq < 32; bq++)
                m = fmaxf(m, tb[(i1+a)*63 + j1 + bq]);
        g_rowmax[h*NN + n1] = m;
    }
}

// ---------------- HMMA tf32 flash attention ----------------
// SMEM (bytes):
//   Kp:  12 ksteps * 128 keys * 4 tid float2      = 49152
//   Vp:  96 d-rows (stride 68 f2) * 16 ks * 4 tid = 52224
//   Ps:  128 x 132 floats                          = 67584
//   TBs: 2205 floats                               = 8820
#define KP_OFF 0
#define VP_OFF 49152
#define PS_OFF 101376
#define TB_OFF 168960
#define SMEM_BYTES 177792

__device__ __forceinline__ void mma_tf32(float c[4], const unsigned a[4], const float2 b) {
    asm volatile(
        "mma.sync.aligned.m16n8k8.row.col.f32.tf32.tf32.f32 "
        "{%0,%1,%2,%3}, {%4,%5,%6,%7}, {%8,%9}, {%0,%1,%2,%3};\n"
        : "+f"(c[0]), "+f"(c[1]), "+f"(c[2]), "+f"(c[3])
        : "r"(__float_as_uint(__shfl_sync(0xffffffffu, 0.f, 0) == 0.f ? 0.f : 0.f)), // placeholder never used
          "r"(0), "r"(0), "r"(0), "r"(0), "r"(0));
}

__global__ void __launch_bounds__(256, 1) flash_mma() {
    extern __shared__ char smem[];
    float2* Kp = (float2*)(smem + KP_OFF);
    float2* Vp = (float2*)(smem + VP_OFF);
    float*  Ps = (float*)(smem + PS_OFF);
    float*  TBs = (float*)(smem + TB_OFF);

    int t = threadIdx.x;
    int w = t >> 5, lane = t & 31;
    int g = lane >> 2, tid = lane & 3;       // mma group / thread-in-group
    int qt = blockIdx.x, bh = blockIdx.y;
    int h = bh & 7, b = bh >> 3;
    int q0 = qt * 128;

    const float* qptr  = g_q  + (long)bh*NN*DD;
    const float* kptr  = g_k  + (long)bh*NN*DD;
    const float* vtptr = g_vt + (long)bh*96*NN;

    // bias table slice rows [qt*4 .. qt*4+34]
    int i1base = qt * 4;
    for (int i = t; i < 2205; i += 256) TBs[i] = g_tb[h*3969 + i1base*63 + i];

    // ---- Q fragments in registers (rows w*16+g, w*16+g+8; 12 ksteps) ----
    unsigned qa[12][4];
    int r0 = q0 + w*16 + g, r1 = r0 + 8;
#pragma unroll
    for (int ks = 0; ks < 12; ks++) {
        int d0 = ks*8 + tid;
        qa[ks][0] = (d0   < 84) ? __float_as_uint(qptr[(long)r0*84 + d0])   : 0u;
        qa[ks][1] = (d0   < 84) ? __float_as_uint(qptr[(long)r1*84 + d0])   : 0u;
        qa[ks][2] = (d0+4 < 84) ? __float_as_uint(qptr[(long)r0*84 + d0+4]) : 0u;
        qa[ks][3] = (d0+4 < 84) ? __float_as_uint(qptr[(long)r1*84 + d0+4]) : 0u;
    }

    // softmax row constants
    float mr0 = g_rowmax[h*NN + r0] + 1.0f;
    float mr1 = g_rowmax[h*NN + r1] + 1.0f;
    int base0 = ((r0 >> 5) - i1base + 31)*63 + (r0 & 31) + 31;
    int base1 = ((r1 >> 5) - i1base + 31)*63 + (r1 & 31) + 31;
    float lacc0 = 0.f, lacc1 = 0.f;

    // O accumulators: 12 d-blocks
    float oc[12][4];
#pragma unroll
    for (int nb = 0; nb < 12; nb++)
#pragma unroll
        for (int j = 0; j < 4; j++) oc[nb][j] = 0.f;

    for (int kt = 0; kt < 8; kt++) {
        int k0 = kt * 128;
        __syncthreads();   // previous tile's Kp/Vp fully consumed

        // ---- stage K tile: Kp[ks][key][tid] = {K[key][ks*8+tid], K[key][ks*8+tid+4]} ----
        for (int i = t; i < 12*128*4; i += 256) {
            int tid4 = i & 3, key = (i >> 2) & 127, ks = i >> 9;
            int d0 = ks*8 + tid4;
            const float* kr = kptr + (long)(k0 + key)*84;
            float2 v;
            v.x = (d0   < 84) ? kr[d0]   : 0.f;
            v.y = (d0+4 < 84) ? kr[d0+4] : 0.f;
            Kp[i] = v;
        }
        // ---- stage V tile: Vp[d*68 + ks*4 + tid] = {V[k0+ks*8+tid][d], V[..+4][d]} ----
        for (int i = t; i < 96*64; i += 256) {
            int tid4 = i & 3, ks = (i >> 2) & 15, d = i >> 6;
            float2 v = make_float2(0.f, 0.f);
            if (d < 84) {
                const float* vr = vtptr + (long)d*NN + k0 + ks*8 + tid4;
                v.x = vr[0]; v.y = vr[4];
            }
            Vp[d*68 + ks*4 + tid4] = v;
        }
        __syncthreads();

        // ---- S = Q @ K^T : 16 n-blocks x 12 k-steps ----
        float sc[16][4];
#pragma unroll
        for (int nb = 0; nb < 16; nb++)
#pragma unroll
            for (int j = 0; j < 4; j++) sc[nb][j] = 0.f;

#pragma unroll
        for (int nb = 0; nb < 16; nb++) {
            const float2* kb = Kp + (nb*8 + g)*4 + tid;
#pragma unroll
            for (int ks = 0; ks < 12; ks++) {
                float2 bfr = kb[ks*512];
                asm volatile(
                    "mma.sync.aligned.m16n8k8.row.col.f32.tf32.tf32.f32 "
                    "{%0,%1,%2,%3}, {%4,%5,%6,%7}, {%8,%9}, {%0,%1,%2,%3};\n"
                    : "+f"(sc[nb][0]), "+f"(sc[nb][1]), "+f"(sc[nb][2]), "+f"(sc[nb][3])
                    : "r"(qa[ks][0]), "r"(qa[ks][1]), "r"(qa[ks][2]), "r"(qa[ks][3]),
                      "r"(__float_as_uint(bfr.x)), "r"(__float_as_uint(bfr.y)));
            }
        }

        // ---- bias + fixed-max softmax; P -> SMEM (warp-private rows) ----
#pragma unroll
        for (int nb = 0; nb < 16; nb++) {
            int n2 = k0 + nb*8 + 2*tid;          // even; n2 and n2+1 share >>5
            int adj = n2 + 31*(n2 >> 5);
            float p0 = __expf(sc[nb][0] + TBs[base0 - adj]     - mr0);
            float p1 = __expf(sc[nb][1] + TBs[base0 - adj - 1] - mr0);
            float p2 = __expf(sc[nb][2] + TBs[base1 - adj]     - mr1);
            float p3 = __expf(sc[nb][3] + TBs[base1 - adj - 1] - mr1);
            lacc0 += p0 + p1;
            lacc1 += p2 + p3;
            int rw0 = w*16 + g, col = nb*8 + 2*tid;
            *(float2*)(Ps + rw0*132 + col)       = make_float2(p0, p1);
            *(float2*)(Ps + (rw0+8)*132 + col)   = make_float2(p2, p3);
        }
        __syncwarp();

        // ---- O += P @ V : 16 k-steps (keys) x 12 n-blocks (d) ----
#pragma unroll
        for (int ks = 0; ks < 16; ks++) {
            unsigned pa[4];
            int rw0 = w*16 + g;
            pa[0] = __float_as_uint(Ps[rw0*132     + ks*8 + tid]);
            pa[1] = __float_as_uint(Ps[(rw0+8)*132 + ks*8 + tid]);
            pa[2] = __float_as_uint(Ps[rw0*132     + ks*8 + tid + 4]);
            pa[3] = __float_as_uint(Ps[(rw0+8)*132 + ks*8 + tid + 4]);
#pragma unroll
            for (int nb = 0; nb < 12; nb++) {
                float2 bfr = Vp[(nb*8 + g)*68 + ks*4 + tid];
                asm volatile(
                    "mma.sync.aligned.m16n8k8.row.col.f32.tf32.tf32.f32 "
                    "{%0,%1,%2,%3}, {%4,%5,%6,%7}, {%8,%9}, {%0,%1,%2,%3};\n"
                    : "+f"(oc[nb][0]), "+f"(oc[nb][1]), "+f"(oc[nb][2]), "+f"(oc[nb][3])
                    : "r"(pa[0]), "r"(pa[1]), "r"(pa[2]), "r"(pa[3]),
                      "r"(__float_as_uint(bfr.x)), "r"(__float_as_uint(bfr.y)));
            }
        }
    }

    // ---- epilogue: quad-reduce l, normalize, scatter ----
    lacc0 += __shfl_xor_sync(0xffffffffu, lacc0, 1);
    lacc0 += __shfl_xor_sync(0xffffffffu, lacc0, 2);
    lacc1 += __shfl_xor_sync(0xffffffffu, lacc1, 1);
    lacc1 += __shfl_xor_sync(0xffffffffu, lacc1, 2);
    float inv0 = 1.0f / lacc0, inv1 = 1.0f / lacc1;

    long cb0 = ((long)(b*NN + r0)*MM)*CC + h*HD;
    long cb1 = ((long)(b*NN + r1)*MM)*CC + h*HD;
#pragma unroll
    for (int nb = 0; nb < 12; nb++) {
#pragma unroll
        for (int e = 0; e < 2; e++) {
            int d84 = nb*8 + 2*tid + e;
            if (d84 < 84) {
                int m = d84 >> 2, dd = d84 & 3;
                g_ctx[cb0 + m*CC + dd] = oc[nb][e]   * inv0;
                g_ctx[cb1 + m*CC + dd] = oc[nb][2+e] * inv1;
            }
        }
    }
}

// ---------------- output projection ----------------
__global__ void __launch_bounds__(256) proj_kernel(const float* __restrict__ W,
                                                   const float* __restrict__ bias,
                                                   float* __restrict__ out) {
    __shared__ float Ws[32*32];
    __shared__ float xs[64][32];
    int t = threadIdx.x;
    for (int i = t; i < 1024; i += 256) Ws[i] = W[i];
    long rowbase = (long)blockIdx.x * 64;
    for (int i = t; i < 64*32; i += 256) {
        int r = i >> 5, c = i & 31;
        xs[r][c] = g_ctx[(rowbase + r)*32 + c];
    }
    __syncthreads();
    int ry = t >> 4, cx = t & 15;
    float acc[4][2] = {};
#pragma unroll
    for (int kk = 0; kk < 32; kk++) {
        float xv[4], wv[2];
#pragma unroll
        for (int u = 0; u < 4; u++) xv[u] = xs[ry*4+u][kk];
        wv[0] = Ws[kk*32 + cx*2];
        wv[1] = Ws[kk*32 + cx*2 + 1];
#pragma unroll
        for (int u = 0; u < 4; u++) { acc[u][0] += xv[u]*wv[0]; acc[u][1] += xv[u]*wv[1]; }
    }
#pragma unroll
    for (int u = 0; u < 4; u++)
#pragma unroll
        for (int v = 0; v < 2; v++)
            out[(rowbase + ry*4 + u)*32 + cx*2 + v] = acc[u][v] + bias[cx*2 + v];
}

// ---------------- launch ----------------
extern "C" void kernel_launch(void* const* d_in, const int* in_sizes, int n_in,
                              void* d_out, int out_size) {
    (void)in_sizes; (void)n_in; (void)out_size;
    const float* x     = (const float*)d_in[0];
    const float* Wqkv  = (const float*)d_in[1];
    const float* bqkv  = (const float*)d_in[2];
    const float* Wproj = (const float*)d_in[3];
    const float* bproj = (const float*)d_in[4];
    const float* Wsq   = (const float*)d_in[5];
    const float* bsq   = (const float*)d_in[6];
    const float* Wdw   = (const float*)d_in[7];
    const float* bdw   = (const float*)d_in[8];
    float* out = (float*)d_out;

    cudaFuncSetAttribute(flash_mma, cudaFuncAttributeMaxDynamicSharedMemorySize, SMEM_BYTES);

    qkv_kernel   <<<NROWS/64, 256>>>(x, Wqkv, bqkv);
    x2_kernel    <<<(BB*NHH*NN)/256, 256>>>(x, Wsq, bsq);
    pool_kernel  <<<BB*NHH, 256>>>();
    conv_kernel  <<<(2*NHH*NN)/256, 256>>>(Wdw, bdw);
    table_kernel <<<dim3(16, NHH), 256>>>();
    rowmax_kernel<<<NHH, 256>>>();
    flash_mma    <<<dim3(NN/128, BB*NHH), 256, SMEM_BYTES>>>();
    proj_kernel  <<<NROWS/64, 256>>>(Wproj, bproj, out);
}

// round 9
// speedup vs baseline: 2.5117x; 1.3721x over previous
#include <cuda_runtime.h>
#include <cstdint>

#define BB   4
#define NHH  8
#define NN   1024
#define MM   21
#define CC   32
#define HD   4
#define DD   84
#define NROWS (BB*NN*MM)

// ---------------- device scratch ----------------
__device__ float g_q[BB*NHH*NN*DD];
__device__ float g_k[BB*NHH*NN*DD];
__device__ float g_v[BB*NHH*NN*DD];      // row-major (bh, n, d84)
__device__ float g_x2[BB*NHH*NN];
__device__ float g_pool[BB*NHH];
__device__ float g_xw[NHH*NN];
__device__ float g_xp[NHH*NN];
__device__ float g_tb[NHH*63*63];
__device__ float g_rowmax[NHH*NN];
__device__ float g_ctx[NROWS*CC];

__device__ __forceinline__ float tf32_hi(float f) {
    return __uint_as_float(__float_as_uint(f) & 0xFFFFE000u);
}

#define MMA_TF32(C, A0, A1, A2, A3, B0, B1) \
    asm volatile( \
        "mma.sync.aligned.m16n8k8.row.col.f32.tf32.tf32.f32 " \
        "{%0,%1,%2,%3}, {%4,%5,%6,%7}, {%8,%9}, {%0,%1,%2,%3};\n" \
        : "+f"((C)[0]), "+f"((C)[1]), "+f"((C)[2]), "+f"((C)[3]) \
        : "r"(A0), "r"(A1), "r"(A2), "r"(A3), "r"(B0), "r"(B1))

// ---------------- kernel A: qkv projection (coalesced writes) + fused x2 ----
// block = 4 token-groups (84 rows of x), 256 threads.
// dyn smem: out[84][100] | xs[84][33] | Ws[32*96] | wsq[84]
#define QKV_OUT 0
#define QKV_XS  8400
#define QKV_WS  (QKV_XS + 84*33)
#define QKV_WSQ (QKV_WS + 3072)
#define QKV_SMEMF (QKV_WSQ + 84)

__global__ void __launch_bounds__(256) qkv2_kernel(const float* __restrict__ x,
                                                   const float* __restrict__ Wq,
                                                   const float* __restrict__ bq,
                                                   const float* __restrict__ Wsq,
                                                   const float* __restrict__ bsq) {
    extern __shared__ float sm[];
    float* out = sm + QKV_OUT;
    float* xs  = sm + QKV_XS;
    float* Ws  = sm + QKV_WS;
    float* wsq = sm + QKV_WSQ;
    int t = threadIdx.x;
    int blk = blockIdx.x;                       // 0..1023, 4 groups each
    long xbase = (long)blk * 84 * 32;

    for (int i = t; i < 84*32; i += 256) xs[(i >> 5)*33 + (i & 31)] = x[xbase + i];
    for (int i = t; i < 3072; i += 256) Ws[i] = Wq[i];
    if (t < 84) wsq[t] = Wsq[t];
    __syncthreads();

    if (t < 252) {
        int ry = t % 84, cg = t / 84;           // cg = which (0:q,1:k,2:v)
        float acc[32];
#pragma unroll
        for (int j = 0; j < 32; j++) acc[j] = bq[cg*32 + j];
        for (int kk = 0; kk < 32; kk++) {
            float xv = xs[ry*33 + kk];
#pragma unroll
            for (int j = 0; j < 32; j++) acc[j] += xv * Ws[kk*96 + cg*32 + j];
        }
#pragma unroll
        for (int j = 0; j < 32; j++) out[ry*100 + cg*32 + j] = acc[j];
    }

    // fused x2: one value per (group, head)
    if (t < 32) {
        int g = t >> 3, h = t & 7;
        float acc = bsq[0];
        for (int m = 0; m < 21; m++)
#pragma unroll
            for (int d = 0; d < 4; d++)
                acc += xs[(g*21 + m)*33 + h*4 + d] * wsq[m*4 + d];
        int b_ = blk*4 + g;
        g_x2[((b_ >> 10)*8 + h)*1024 + (b_ & 1023)] = acc;
    }
    __syncthreads();

    // coalesced write-out: 96 rows (4 groups x 8 heads x 3 tensors) of 84 floats
    int w = t >> 5, lane = t & 31;
#pragma unroll
    for (int it = 0; it < 12; it++) {
        int tk = w*12 + it;
        int g = tk / 24, rem = tk % 24, which = rem >> 3, h = rem & 7;
        int b_ = blk*4 + g;
        int bh = (b_ >> 10)*8 + h, n = b_ & 1023;
        float* dst = (which == 0 ? g_q : which == 1 ? g_k : g_v)
                     + ((long)bh*1024 + n)*84;
        for (int d84 = lane; d84 < 84; d84 += 32) {
            float s = out[(g*21 + (d84 >> 2))*100 + which*32 + h*4 + (d84 & 3)];
            dst[d84] = (which == 0) ? s * 0.03125f : s;
        }
    }
}

// ---------------- LSPE small kernels ----------------
__global__ void pool_kernel() {
    int bh = blockIdx.x, t = threadIdx.x;
    const float* p = g_x2 + bh*NN;
    float s = 0.f, mx = -1e30f;
    for (int i = t; i < NN; i += 256) { float v = p[i]; s += v; mx = fmaxf(mx, v); }
    __shared__ float ss[256], sm_[256];
    ss[t] = s; sm_[t] = mx;
    __syncthreads();
    for (int o = 128; o > 0; o >>= 1) {
        if (t < o) { ss[t] += ss[t+o]; sm_[t] = fmaxf(sm_[t], sm_[t+o]); }
        __syncthreads();
    }
    if (t == 0) g_pool[bh] = ss[0]*(1.f/1024.f) + sm_[0];
}

__global__ void conv_kernel(const float* __restrict__ Wdw,
                            const float* __restrict__ bdw) {
    int idx = blockIdx.x*256 + threadIdx.x;
    int pos = idx & 1023, o = idx >> 10;
    int y = pos >> 5, xx = pos & 31;
    int ic = o >> 1;
    float acc = 0.f;
    for (int b = 0; b < BB; b++) {
        const float* src = g_x2 + (b*NHH + ic)*NN;
        float c = bdw[o] + g_pool[b*NHH + (o & 7)];
#pragma unroll
        for (int ky = 0; ky < 3; ky++) {
            int yy = y + ky - 1; if (yy < 0 || yy >= 32) continue;
#pragma unroll
            for (int kx = 0; kx < 3; kx++) {
                int x2i = xx + kx - 1; if (x2i < 0 || x2i >= 32) continue;
                c += src[yy*32 + x2i] * Wdw[o*9 + ky*3 + kx];
            }
        }
        acc += c;
    }
    acc *= 0.25f;
    if (o < 8) g_xw[o*NN + pos] = acc;
    else       g_xp[(o-8)*NN + pos] = acc;
}

__global__ void table_kernel() {
    int h = blockIdx.y, t = threadIdx.x;
    __shared__ float xw[1024], xp[1024];
    for (int i = t; i < 1024; i += 256) { xw[i] = g_xw[h*NN + i]; xp[i] = g_xp[h*NN + i]; }
    __syncthreads();
    int pq = blockIdx.x*256 + t;
    if (pq < 63*63) {
        int p = pq / 63, q = pq % 63;
        float acc = 0.f;
        int alo = max(0, p-31), ahi = min(31, p);
        int blo = max(0, q-31), bhi = min(31, q);
        for (int a = alo; a <= ahi; a++)
            for (int b2 = blo; b2 <= bhi; b2++)
                acc += xw[a*32 + b2] * xp[(p-a)*32 + (q-b2)];
        g_tb[h*3969 + pq] = acc;
    }
}

__global__ void rowmax_kernel() {
    int h = blockIdx.x, t = threadIdx.x;
    __shared__ float tb[3969];
    for (int i = t; i < 3969; i += 256) tb[i] = g_tb[h*3969 + i];
    __syncthreads();
    for (int n1 = t; n1 < 1024; n1 += 256) {
        int i1 = n1 >> 5, j1 = n1 & 31;
        float m = -1e30f;
        for (int a = 0; a < 32; a++)
#pragma unroll 4
            for (int bq = 0; bq < 32; bq++)
                m = fmaxf(m, tb[(i1+a)*63 + j1 + bq]);
        g_rowmax[h*NN + n1] = m;
    }
}

// ---------------- HMMA tf32 flash attention (BN=64, split-tf32 PV) --------
// SMEM bytes:
//   Kp : 11 ks * 64 keys * 4 tid float2      = 22528
//   Vhi: 88 d-rows * 36 f2 (pad)             = 25344
//   Vlo: same                                 = 25344
//   TBs: 2205 floats                          = 8820
#define KP_OFF 0
#define VH_OFF 22528
#define VL_OFF 47872
#define TB_OFF 73216
#define SMEM_BYTES 82048

__global__ void __launch_bounds__(256, 2) flash_mma() {
    extern __shared__ char smem[];
    float2* Kp  = (float2*)(smem + KP_OFF);
    float*  VHw = (float*)(smem + VH_OFF);
    float*  VLw = (float*)(smem + VL_OFF);
    float2* VH2 = (float2*)(smem + VH_OFF);
    float2* VL2 = (float2*)(smem + VL_OFF);
    float*  TBs = (float*)(smem + TB_OFF);

    int t = threadIdx.x;
    int w = t >> 5, lane = t & 31;
    int g = lane >> 2, tid = lane & 3;
    int qt = blockIdx.x, bh = blockIdx.y;
    int h = bh & 7, b = bh >> 3;
    int q0 = qt * 128;

    const float* qptr = g_q + (long)bh*NN*DD;
    const float* kptr = g_k + (long)bh*NN*DD;
    const float* vptr = g_v + (long)bh*NN*DD;

    // bias table slice rows [qt*4 .. qt*4+34]
    int i1base = qt * 4;
    for (int i = t; i < 2205; i += 256) TBs[i] = g_tb[h*3969 + i1base*63 + i];
    // zero padded V rows 84..87 (never written by staging)
    for (int i = t; i < 4*36; i += 256) {
        int r = 84 + (i / 36), c = i % 36;
        VH2[r*36 + c] = make_float2(0.f, 0.f);
        VL2[r*36 + c] = make_float2(0.f, 0.f);
    }

    // Q fragments in registers: rows r0 = q0+w*16+g, r1 = r0+8; 11 ksteps
    unsigned qa[11][4];
    int r0 = q0 + w*16 + g, r1 = r0 + 8;
#pragma unroll
    for (int ks = 0; ks < 11; ks++) {
        int d0 = ks*8 + tid;
        qa[ks][0] = __float_as_uint(qptr[(long)r0*84 + d0]);
        qa[ks][1] = __float_as_uint(qptr[(long)r1*84 + d0]);
        qa[ks][2] = (d0+4 < 84) ? __float_as_uint(qptr[(long)r0*84 + d0+4]) : 0u;
        qa[ks][3] = (d0+4 < 84) ? __float_as_uint(qptr[(long)r1*84 + d0+4]) : 0u;
    }

    float mr0 = g_rowmax[h*NN + r0] + 1.0f;
    float mr1 = g_rowmax[h*NN + r1] + 1.0f;
    int base0 = ((r0 >> 5) - i1base + 31)*63 + (r0 & 31) + 31;
    int base1 = ((r1 >> 5) - i1base + 31)*63 + (r1 & 31) + 31;
    float lacc0 = 0.f, lacc1 = 0.f;

    float oc[11][4];
#pragma unroll
    for (int db = 0; db < 11; db++)
#pragma unroll
        for (int j = 0; j < 4; j++) oc[db][j] = 0.f;

    int la = (lane & ~3) | (tid >> 1);
    int lb = la + 2;
    bool odd = tid & 1;

    for (int kt = 0; kt < 16; kt++) {
        int k0 = kt * 64;
        __syncthreads();

        // ---- stage K: Kp[ks][key][tid] = {K[key][ks*8+tid], K[key][ks*8+tid+4]} ----
        for (int i = t; i < 11*64*4; i += 256) {
            int tid4 = i & 3, key = (i >> 2) & 63, ks = i >> 8;
            int d0 = ks*8 + tid4;
            const float* kr = kptr + (long)(k0 + key)*84;
            float2 v;
            v.x = kr[d0];
            v.y = (d0+4 < 84) ? kr[d0+4] : 0.f;
            Kp[i] = v;
        }
        // ---- stage V (hi/lo): word (d*72 + ks*8 + tid*2 + half) ----
        for (int i = t; i < 64*21; i += 256) {
            int key = i / 21, dg = i % 21;
            float4 v = *(const float4*)(vptr + (long)(k0 + key)*84 + dg*4);
            int ks = key >> 3, kk = key & 7;
            int tid4 = kk & 3, half = kk >> 2;
            int wb = (dg*4)*72 + ks*8 + tid4*2 + half;
            float vs[4] = {v.x, v.y, v.z, v.w};
#pragma unroll
            for (int j = 0; j < 4; j++) {
                float hv = tf32_hi(vs[j]);
                VHw[wb + j*72] = hv;
                VLw[wb + j*72] = vs[j] - hv;
            }
        }
        __syncthreads();

        for (int nb = 0; nb < 8; nb++) {
            // ---- S block: 11 QK MMAs ----
            float c[4] = {0.f, 0.f, 0.f, 0.f};
            const float2* kb = Kp + (nb*8 + g)*4 + tid;
#pragma unroll
            for (int ks = 0; ks < 11; ks++) {
                float2 bf = kb[ks*256];
                MMA_TF32(c, qa[ks][0], qa[ks][1], qa[ks][2], qa[ks][3],
                         __float_as_uint(bf.x), __float_as_uint(bf.y));
            }
            // ---- bias + fixed-max softmax ----
            int n2 = k0 + nb*8 + 2*tid;
            int adj = n2 + 31*(n2 >> 5);
            float p0 = __expf(c[0] + TBs[base0 - adj]     - mr0);
            float p1 = __expf(c[1] + TBs[base0 - adj - 1] - mr0);
            float p2 = __expf(c[2] + TBs[base1 - adj]     - mr1);
            float p3 = __expf(c[3] + TBs[base1 - adj - 1] - mr1);
            lacc0 += p0 + p1;
            lacc1 += p2 + p3;
            // ---- C-frag -> A-frag via quad shuffles ----
            float s0 = __shfl_sync(0xffffffffu, p0, la);
            float s1 = __shfl_sync(0xffffffffu, p1, la);
            float s2 = __shfl_sync(0xffffffffu, p2, la);
            float s3 = __shfl_sync(0xffffffffu, p3, la);
            float s4 = __shfl_sync(0xffffffffu, p0, lb);
            float s5 = __shfl_sync(0xffffffffu, p1, lb);
            float s6 = __shfl_sync(0xffffffffu, p2, lb);
            float s7 = __shfl_sync(0xffffffffu, p3, lb);
            float a0 = odd ? s1 : s0;      // (row g,   col tid)
            float a1 = odd ? s3 : s2;      // (row g+8, col tid)
            float a2 = odd ? s5 : s4;      // (row g,   col tid+4)
            float a3 = odd ? s7 : s6;      // (row g+8, col tid+4)
            float l0 = a0 - tf32_hi(a0);
            float l1 = a1 - tf32_hi(a1);
            float l2 = a2 - tf32_hi(a2);
            float l3 = a3 - tf32_hi(a3);
            unsigned ua0 = __float_as_uint(a0), ua1 = __float_as_uint(a1);
            unsigned ua2 = __float_as_uint(a2), ua3 = __float_as_uint(a3);
            unsigned ul0 = __float_as_uint(l0), ul1 = __float_as_uint(l1);
            unsigned ul2 = __float_as_uint(l2), ul3 = __float_as_uint(l3);
            // ---- PV: 11 d-blocks x 3 MMAs (split-tf32) ----
            const float2* vhb = VH2 + nb*4 + tid;
            const float2* vlb = VL2 + nb*4 + tid;
#pragma unroll
            for (int db = 0; db < 11; db++) {
                float2 bh_ = vhb[(db*8 + g)*36];
                float2 bl_ = vlb[(db*8 + g)*36];
                unsigned bhx = __float_as_uint(bh_.x), bhy = __float_as_uint(bh_.y);
                MMA_TF32(oc[db], ua0, ua1, ua2, ua3, bhx, bhy);
                MMA_TF32(oc[db], ul0, ul1, ul2, ul3, bhx, bhy);
                MMA_TF32(oc[db], ua0, ua1, ua2, ua3,
                         __float_as_uint(bl_.x), __float_as_uint(bl_.y));
            }
        }
    }

    // ---- epilogue: quad-reduce l, normalize, scatter ----
    lacc0 += __shfl_xor_sync(0xffffffffu, lacc0, 1);
    lacc0 += __shfl_xor_sync(0xffffffffu, lacc0, 2);
    lacc1 += __shfl_xor_sync(0xffffffffu, lacc1, 1);
    lacc1 += __shfl_xor_sync(0xffffffffu, lacc1, 2);
    float inv0 = 1.0f / lacc0, inv1 = 1.0f / lacc1;

    long cb0 = ((long)(b*NN + r0)*MM)*CC + h*HD;
    long cb1 = ((long)(b*NN + r1)*MM)*CC + h*HD;
#pragma unroll
    for (int db = 0; db < 11; db++) {
#pragma unroll
        for (int e = 0; e < 2; e++) {
            int d84 = db*8 + 2*tid + e;
            if (d84 < 84) {
                int m = d84 >> 2, dd = d84 & 3;
                g_ctx[cb0 + m*CC + dd] = oc[db][e]   * inv0;
                g_ctx[cb1 + m*CC + dd] = oc[db][2+e] * inv1;
            }
        }
    }
}

// ---------------- output projection ----------------
__global__ void __launch_bounds__(256) proj_kernel(const float* __restrict__ W,
                                                   const float* __restrict__ bias,
                                                   float* __restrict__ out) {
    __shared__ float Ws[32*32];
    __shared__ float xs[64][32];
    int t = threadIdx.x;
    for (int i = t; i < 1024; i += 256) Ws[i] = W[i];
    long rowbase = (long)blockIdx.x * 64;
    for (int i = t; i < 64*32; i += 256) {
        int r = i >> 5, c = i & 31;
        xs[r][c] = g_ctx[(rowbase + r)*32 + c];
    }
    __syncthreads();
    int ry = t >> 4, cx = t & 15;
    float acc[4][2] = {};
#pragma unroll
    for (int kk = 0; kk < 32; kk++) {
        float xv[4], wv[2];
#pragma unroll
        for (int u = 0; u < 4; u++) xv[u] = xs[ry*4+u][kk];
        wv[0] = Ws[kk*32 + cx*2];
        wv[1] = Ws[kk*32 + cx*2 + 1];
#pragma unroll
        for (int u = 0; u < 4; u++) { acc[u][0] += xv[u]*wv[0]; acc[u][1] += xv[u]*wv[1]; }
    }
#pragma unroll
    for (int u = 0; u < 4; u++)
#pragma unroll
        for (int v = 0; v < 2; v++)
            out[(rowbase + ry*4 + u)*32 + cx*2 + v] = acc[u][v] + bias[cx*2 + v];
}

// ---------------- launch ----------------
extern "C" void kernel_launch(void* const* d_in, const int* in_sizes, int n_in,
                              void* d_out, int out_size) {
    (void)in_sizes; (void)n_in; (void)out_size;
    const float* x     = (const float*)d_in[0];
    const float* Wqkv  = (const float*)d_in[1];
    const float* bqkv  = (const float*)d_in[2];
    const float* Wproj = (const float*)d_in[3];
    const float* bproj = (const float*)d_in[4];
    const float* Wsq   = (const float*)d_in[5];
    const float* bsq   = (const float*)d_in[6];
    const float* Wdw   = (const float*)d_in[7];
    const float* bdw   = (const float*)d_in[8];
    float* out = (float*)d_out;

    cudaFuncSetAttribute(flash_mma, cudaFuncAttributeMaxDynamicSharedMemorySize, SMEM_BYTES);
    cudaFuncSetAttribute(qkv2_kernel, cudaFuncAttributeMaxDynamicSharedMemorySize,
                         QKV_SMEMF * (int)sizeof(float));

    qkv2_kernel  <<<1024, 256, QKV_SMEMF*sizeof(float)>>>(x, Wqkv, bqkv, Wsq, bsq);
    pool_kernel  <<<BB*NHH, 256>>>();
    conv_kernel  <<<(2*NHH*NN)/256, 256>>>(Wdw, bdw);
    table_kernel <<<dim3(16, NHH), 256>>>();
    rowmax_kernel<<<NHH, 256>>>();
    flash_mma    <<<dim3(NN/128, BB*NHH), 256, SMEM_BYTES>>>();
    proj_kernel  <<<NROWS/64, 256>>>(Wproj, bproj, out);
}

// round 12
// speedup vs baseline: 2.9177x; 1.1617x over previous
#include <cuda_runtime.h>
#include <cstdint>

#define BB   4
#define NHH  8
#define NN   1024
#define MM   21
#define CC   32
#define HD   4
#define DD   84
#define NROWS (BB*NN*MM)

// ---------------- device scratch ----------------
__device__ float g_q[BB*NHH*NN*DD];
__device__ float g_k[BB*NHH*NN*DD];
__device__ float g_v[BB*NHH*NN*DD];      // row-major (bh, n, d84)
__device__ float g_x2[BB*NHH*NN];
__device__ float g_pool[BB*NHH];
__device__ float g_xw[NHH*NN];
__device__ float g_xp[NHH*NN];
__device__ float g_tb[NHH*63*63];
__device__ float g_rowmax[NHH*NN];
__device__ float g_ctx[NROWS*CC];

__device__ __forceinline__ float tf32_hi(float f) {
    return __uint_as_float(__float_as_uint(f) & 0xFFFFE000u);
}
__device__ __forceinline__ unsigned tf32_rnd(float f) {
    return (__float_as_uint(f) + 0x1000u) & 0xFFFFE000u;
}

#define MMA_TF32(C, A0, A1, A2, A3, B0, B1) \
    asm volatile( \
        "mma.sync.aligned.m16n8k8.row.col.f32.tf32.tf32.f32 " \
        "{%0,%1,%2,%3}, {%4,%5,%6,%7}, {%8,%9}, {%0,%1,%2,%3};\n" \
        : "+f"((C)[0]), "+f"((C)[1]), "+f"((C)[2]), "+f"((C)[3]) \
        : "r"(A0), "r"(A1), "r"(A2), "r"(A3), "r"(B0), "r"(B1))

// ---------------- kernel A: qkv projection (coalesced writes) + fused x2 ----
#define QKV_OUT 0
#define QKV_XS  8400
#define QKV_WS  (QKV_XS + 84*33)
#define QKV_WSQ (QKV_WS + 3072)
#define QKV_SMEMF (QKV_WSQ + 84)

__global__ void __launch_bounds__(256) qkv2_kernel(const float* __restrict__ x,
                                                   const float* __restrict__ Wq,
                                                   const float* __restrict__ bq,
                                                   const float* __restrict__ Wsq,
                                                   const float* __restrict__ bsq) {
    extern __shared__ float sm[];
    float* out = sm + QKV_OUT;
    float* xs  = sm + QKV_XS;
    float* Ws  = sm + QKV_WS;
    float* wsq = sm + QKV_WSQ;
    int t = threadIdx.x;
    int blk = blockIdx.x;                       // 0..1023, 4 groups each
    long xbase = (long)blk * 84 * 32;

    for (int i = t; i < 84*32; i += 256) xs[(i >> 5)*33 + (i & 31)] = x[xbase + i];
    for (int i = t; i < 3072; i += 256) Ws[i] = Wq[i];
    if (t < 84) wsq[t] = Wsq[t];
    __syncthreads();

    if (t < 252) {
        int ry = t % 84, cg = t / 84;           // cg = which (0:q,1:k,2:v)
        float acc[32];
#pragma unroll
        for (int j = 0; j < 32; j++) acc[j] = bq[cg*32 + j];
        for (int kk = 0; kk < 32; kk++) {
            float xv = xs[ry*33 + kk];
#pragma unroll
            for (int j = 0; j < 32; j++) acc[j] += xv * Ws[kk*96 + cg*32 + j];
        }
#pragma unroll
        for (int j = 0; j < 32; j++) out[ry*100 + cg*32 + j] = acc[j];
    }

    // fused x2: one value per (group, head)
    if (t < 32) {
        int g = t >> 3, h = t & 7;
        float acc = bsq[0];
        for (int m = 0; m < 21; m++)
#pragma unroll
            for (int d = 0; d < 4; d++)
                acc += xs[(g*21 + m)*33 + h*4 + d] * wsq[m*4 + d];
        int b_ = blk*4 + g;
        g_x2[((b_ >> 10)*8 + h)*1024 + (b_ & 1023)] = acc;
    }
    __syncthreads();

    // coalesced write-out: 96 rows (4 groups x 8 heads x 3 tensors) of 84 floats
    int w = t >> 5, lane = t & 31;
#pragma unroll
    for (int it = 0; it < 12; it++) {
        int tk = w*12 + it;
        int g = tk / 24, rem = tk % 24, which = rem >> 3, h = rem & 7;
        int b_ = blk*4 + g;
        int bh = (b_ >> 10)*8 + h, n = b_ & 1023;
        float* dst = (which == 0 ? g_q : which == 1 ? g_k : g_v)
                     + ((long)bh*1024 + n)*84;
        for (int d84 = lane; d84 < 84; d84 += 32) {
            float s = out[(g*21 + (d84 >> 2))*100 + which*32 + h*4 + (d84 & 3)];
            dst[d84] = (which == 0) ? s * 0.03125f : s;
        }
    }
}

// ---------------- LSPE small kernels ----------------
__global__ void pool_kernel() {
    int bh = blockIdx.x, t = threadIdx.x;
    const float* p = g_x2 + bh*NN;
    float s = 0.f, mx = -1e30f;
    for (int i = t; i < NN; i += 256) { float v = p[i]; s += v; mx = fmaxf(mx, v); }
    __shared__ float ss[256], sm_[256];
    ss[t] = s; sm_[t] = mx;
    __syncthreads();
    for (int o = 128; o > 0; o >>= 1) {
        if (t < o) { ss[t] += ss[t+o]; sm_[t] = fmaxf(sm_[t], sm_[t+o]); }
        __syncthreads();
    }
    if (t == 0) g_pool[bh] = ss[0]*(1.f/1024.f) + sm_[0];
}

__global__ void conv_kernel(const float* __restrict__ Wdw,
                            const float* __restrict__ bdw) {
    int idx = blockIdx.x*256 + threadIdx.x;
    int pos = idx & 1023, o = idx >> 10;
    int y = pos >> 5, xx = pos & 31;
    int ic = o >> 1;
    float acc = 0.f;
    for (int b = 0; b < BB; b++) {
        const float* src = g_x2 + (b*NHH + ic)*NN;
        float c = bdw[o] + g_pool[b*NHH + (o & 7)];
#pragma unroll
        for (int ky = 0; ky < 3; ky++) {
            int yy = y + ky - 1; if (yy < 0 || yy >= 32) continue;
#pragma unroll
            for (int kx = 0; kx < 3; kx++) {
                int x2i = xx + kx - 1; if (x2i < 0 || x2i >= 32) continue;
                c += src[yy*32 + x2i] * Wdw[o*9 + ky*3 + kx];
            }
        }
        acc += c;
    }
    acc *= 0.25f;
    if (o < 8) g_xw[o*NN + pos] = acc;
    else       g_xp[(o-8)*NN + pos] = acc;
}

// table: grid (63, 8); 4 threads per output (split a-range), quad-shuffle reduce
__global__ void __launch_bounds__(256) table_kernel() {
    int p = blockIdx.x, h = blockIdx.y, t = threadIdx.x;
    __shared__ float xw[1024], xp[1024];
    for (int i = t; i < 1024; i += 256) { xw[i] = g_xw[h*NN + i]; xp[i] = g_xp[h*NN + i]; }
    __syncthreads();
    int q = t >> 2, part = t & 3;            // q 0..63 (63 invalid -> empty loop)
    int alo = max(0, p-31), ahi = min(31, p);
    int blo = max(0, q-31), bhi = min(31, q);
    float acc = 0.f;
    for (int a = alo + part; a <= ahi; a += 4) {
        const float* xwr = xw + a*32;
        const float* xpr = xp + (p-a)*32 - blo;
#pragma unroll 4
        for (int b2 = blo; b2 <= bhi; b2++)
            acc += xwr[b2] * xpr[q - b2];    // xp[(p-a)*32 + (q-b2)]
    }
    acc += __shfl_xor_sync(0xffffffffu, acc, 1);
    acc += __shfl_xor_sync(0xffffffffu, acc, 2);
    if (part == 0 && q < 63) g_tb[h*3969 + p*63 + q] = acc;
}

// rowmax: separable 32x32 window max (col-max pass, then row-max pass)
__global__ void __launch_bounds__(256) rowmax_kernel() {
    int h = blockIdx.x, t = threadIdx.x;
    __shared__ float tb[3969];
    __shared__ float cm[32*63];
    for (int i = t; i < 3969; i += 256) tb[i] = g_tb[h*3969 + i];
    __syncthreads();
    for (int i = t; i < 32*63; i += 256) {
        int i1 = i / 63, j = i % 63;
        float m = tb[i1*63 + j];
#pragma unroll 4
        for (int a = 1; a < 32; a++) m = fmaxf(m, tb[(i1+a)*63 + j]);
        cm[i] = m;
    }
    __syncthreads();
    for (int n1 = t; n1 < 1024; n1 += 256) {
        int i1 = n1 >> 5, j1 = n1 & 31;
        float m = cm[i1*63 + j1];
#pragma unroll 4
        for (int b = 1; b < 32; b++) m = fmaxf(m, cm[i1*63 + j1 + b]);
        g_rowmax[h*NN + n1] = m;
    }
}

// ---------------- HMMA tf32 flash attention (BN=64, rounded-P + split-V PV) --
#define KP_OFF 0
#define VH_OFF 22528
#define VL_OFF 47872
#define TB_OFF 73216
#define SMEM_BYTES 82048

__global__ void __launch_bounds__(256, 2) flash_mma() {
    extern __shared__ char smem[];
    float2* Kp  = (float2*)(smem + KP_OFF);
    float*  VHw = (float*)(smem + VH_OFF);
    float*  VLw = (float*)(smem + VL_OFF);
    float2* VH2 = (float2*)(smem + VH_OFF);
    float2* VL2 = (float2*)(smem + VL_OFF);
    float*  TBs = (float*)(smem + TB_OFF);

    int t = threadIdx.x;
    int w = t >> 5, lane = t & 31;
    int g = lane >> 2, tid = lane & 3;
    int qt = blockIdx.x, bh = blockIdx.y;
    int h = bh & 7, b = bh >> 3;
    int q0 = qt * 128;

    const float* qptr = g_q + (long)bh*NN*DD;
    const float* kptr = g_k + (long)bh*NN*DD;
    const float* vptr = g_v + (long)bh*NN*DD;

    // bias table slice rows [qt*4 .. qt*4+34]
    int i1base = qt * 4;
    for (int i = t; i < 2205; i += 256) TBs[i] = g_tb[h*3969 + i1base*63 + i];
    // zero padded V rows 84..87
    for (int i = t; i < 4*36; i += 256) {
        int r = 84 + (i / 36), c = i % 36;
        VH2[r*36 + c] = make_float2(0.f, 0.f);
        VL2[r*36 + c] = make_float2(0.f, 0.f);
    }

    // Q fragments: rows r0 = q0+w*16+g, r1 = r0+8; 11 ksteps
    unsigned qa[11][4];
    int r0 = q0 + w*16 + g, r1 = r0 + 8;
#pragma unroll
    for (int ks = 0; ks < 11; ks++) {
        int d0 = ks*8 + tid;
        qa[ks][0] = __float_as_uint(qptr[(long)r0*84 + d0]);
        qa[ks][1] = __float_as_uint(qptr[(long)r1*84 + d0]);
        qa[ks][2] = (d0+4 < 84) ? __float_as_uint(qptr[(long)r0*84 + d0+4]) : 0u;
        qa[ks][3] = (d0+4 < 84) ? __float_as_uint(qptr[(long)r1*84 + d0+4]) : 0u;
    }

    float mr0 = g_rowmax[h*NN + r0] + 1.0f;
    float mr1 = g_rowmax[h*NN + r1] + 1.0f;
    int base0 = ((r0 >> 5) - i1base + 31)*63 + (r0 & 31) + 31;
    int base1 = ((r1 >> 5) - i1base + 31)*63 + (r1 & 31) + 31;
    float lacc0 = 0.f, lacc1 = 0.f;

    float oc[11][4];
#pragma unroll
    for (int db = 0; db < 11; db++)
#pragma unroll
        for (int j = 0; j < 4; j++) oc[db][j] = 0.f;

    int la = (lane & ~3) | (tid >> 1);
    int lb = la + 2;
    bool odd = tid & 1;

    for (int kt = 0; kt < 16; kt++) {
        int k0 = kt * 64;
        __syncthreads();

        // ---- stage K: Kp[ks][key][tid] = {K[key][ks*8+tid], K[key][ks*8+tid+4]} ----
        for (int i = t; i < 11*64*4; i += 256) {
            int tid4 = i & 3, key = (i >> 2) & 63, ks = i >> 8;
            int d0 = ks*8 + tid4;
            const float* kr = kptr + (long)(k0 + key)*84;
            float2 v;
            v.x = kr[d0];
            v.y = (d0+4 < 84) ? kr[d0+4] : 0.f;
            Kp[i] = v;
        }
        // ---- stage V (hi/lo) ----
        for (int i = t; i < 64*21; i += 256) {
            int key = i / 21, dg = i % 21;
            float4 v = *(const float4*)(vptr + (long)(k0 + key)*84 + dg*4);
            int ks = key >> 3, kk = key & 7;
            int tid4 = kk & 3, half = kk >> 2;
            int wb = (dg*4)*72 + ks*8 + tid4*2 + half;
            float vs[4] = {v.x, v.y, v.z, v.w};
#pragma unroll
            for (int j = 0; j < 4; j++) {
                float hv = tf32_hi(vs[j]);
                VHw[wb + j*72] = hv;
                VLw[wb + j*72] = vs[j] - hv;
            }
        }
        __syncthreads();

        for (int nb = 0; nb < 8; nb++) {
            // ---- S block: 11 QK MMAs ----
            float c[4] = {0.f, 0.f, 0.f, 0.f};
            const float2* kb = Kp + (nb*8 + g)*4 + tid;
#pragma unroll
            for (int ks = 0; ks < 11; ks++) {
                float2 bf = kb[ks*256];
                MMA_TF32(c, qa[ks][0], qa[ks][1], qa[ks][2], qa[ks][3],
                         __float_as_uint(bf.x), __float_as_uint(bf.y));
            }
            // ---- bias + fixed-max softmax ----
            int n2 = k0 + nb*8 + 2*tid;
            int adj = n2 + 31*(n2 >> 5);
            float p0 = __expf(c[0] + TBs[base0 - adj]     - mr0);
            float p1 = __expf(c[1] + TBs[base0 - adj - 1] - mr0);
            float p2 = __expf(c[2] + TBs[base1 - adj]     - mr1);
            float p3 = __expf(c[3] + TBs[base1 - adj - 1] - mr1);
            lacc0 += p0 + p1;
            lacc1 += p2 + p3;
            // ---- C-frag -> A-frag via quad shuffles; round P to tf32 ----
            float s0 = __shfl_sync(0xffffffffu, p0, la);
            float s1 = __shfl_sync(0xffffffffu, p1, la);
            float s2 = __shfl_sync(0xffffffffu, p2, la);
            float s3 = __shfl_sync(0xffffffffu, p3, la);
            float s4 = __shfl_sync(0xffffffffu, p0, lb);
            float s5 = __shfl_sync(0xffffffffu, p1, lb);
            float s6 = __shfl_sync(0xffffffffu, p2, lb);
            float s7 = __shfl_sync(0xffffffffu, p3, lb);
            unsigned ua0 = tf32_rnd(odd ? s1 : s0);   // (row g,   col tid)
            unsigned ua1 = tf32_rnd(odd ? s3 : s2);   // (row g+8, col tid)
            unsigned ua2 = tf32_rnd(odd ? s5 : s4);   // (row g,   col tid+4)
            unsigned ua3 = tf32_rnd(odd ? s7 : s6);   // (row g+8, col tid+4)
            // ---- PV: 11 d-blocks x 2 MMAs (tf32(P)*(Vhi+Vlo) = tf32(P)*V) ----
            const float2* vhb = VH2 + nb*4 + tid;
            const float2* vlb = VL2 + nb*4 + tid;
#pragma unroll
            for (int db = 0; db < 11; db++) {
                float2 bh_ = vhb[(db*8 + g)*36];
                float2 bl_ = vlb[(db*8 + g)*36];
                MMA_TF32(oc[db], ua0, ua1, ua2, ua3,
                         __float_as_uint(bh_.x), __float_as_uint(bh_.y));
                MMA_TF32(oc[db], ua0, ua1, ua2, ua3,
                         __float_as_uint(bl_.x), __float_as_uint(bl_.y));
            }
        }
    }

    // ---- epilogue: quad-reduce l, normalize, scatter ----
    lacc0 += __shfl_xor_sync(0xffffffffu, lacc0, 1);
    lacc0 += __shfl_xor_sync(0xffffffffu, lacc0, 2);
    lacc1 += __shfl_xor_sync(0xffffffffu, lacc1, 1);
    lacc1 += __shfl_xor_sync(0xffffffffu, lacc1, 2);
    float inv0 = 1.0f / lacc0, inv1 = 1.0f / lacc1;

    long cb0 = ((long)(b*NN + r0)*MM)*CC + h*HD;
    long cb1 = ((long)(b*NN + r1)*MM)*CC + h*HD;
#pragma unroll
    for (int db = 0; db < 11; db++) {
#pragma unroll
        for (int e = 0; e < 2; e++) {
            int d84 = db*8 + 2*tid + e;
            if (d84 < 84) {
                int m = d84 >> 2, dd = d84 & 3;
                g_ctx[cb0 + m*CC + dd] = oc[db][e]   * inv0;
                g_ctx[cb1 + m*CC + dd] = oc[db][2+e] * inv1;
            }
        }
    }
}

// ---------------- output projection ----------------
__global__ void __launch_bounds__(256) proj_kernel(const float* __restrict__ W,
                                                   const float* __restrict__ bias,
                                                   float* __restrict__ out) {
    __shared__ float Ws[32*32];
    __shared__ float xs[64][32];
    int t = threadIdx.x;
    for (int i = t; i < 1024; i += 256) Ws[i] = W[i];
    long rowbase = (long)blockIdx.x * 64;
    for (int i = t; i < 64*32; i += 256) {
        int r = i >> 5, c = i & 31;
        xs[r][c] = g_ctx[(rowbase + r)*32 + c];
    }
    __syncthreads();
    int ry = t >> 4, cx = t & 15;
    float acc[4][2] = {};
#pragma unroll
    for (int kk = 0; kk < 32; kk++) {
        float xv[4], wv[2];
#pragma unroll
        for (int u = 0; u < 4; u++) xv[u] = xs[ry*4+u][kk];
        wv[0] = Ws[kk*32 + cx*2];
        wv[1] = Ws[kk*32 + cx*2 + 1];
#pragma unroll
        for (int u = 0; u < 4; u++) { acc[u][0] += xv[u]*wv[0]; acc[u][1] += xv[u]*wv[1]; }
    }
#pragma unroll
    for (int u = 0; u < 4; u++)
#pragma unroll
        for (int v = 0; v < 2; v++)
            out[(rowbase + ry*4 + u)*32 + cx*2 + v] = acc[u][v] + bias[cx*2 + v];
}

// ---------------- launch ----------------
extern "C" void kernel_launch(void* const* d_in, const int* in_sizes, int n_in,
                              void* d_out, int out_size) {
    (void)in_sizes; (void)n_in; (void)out_size;
    const float* x     = (const float*)d_in[0];
    const float* Wqkv  = (const float*)d_in[1];
    const float* bqkv  = (const float*)d_in[2];
    const float* Wproj = (const float*)d_in[3];
    const float* bproj = (const float*)d_in[4];
    const float* Wsq   = (const float*)d_in[5];
    const float* bsq   = (const float*)d_in[6];
    const float* Wdw   = (const float*)d_in[7];
    const float* bdw   = (const float*)d_in[8];
    float* out = (float*)d_out;

    cudaFuncSetAttribute(flash_mma, cudaFuncAttributeMaxDynamicSharedMemorySize, SMEM_BYTES);
    cudaFuncSetAttribute(qkv2_kernel, cudaFuncAttributeMaxDynamicSharedMemorySize,
                         QKV_SMEMF * (int)sizeof(float));

    qkv2_kernel  <<<1024, 256, QKV_SMEMF*sizeof(float)>>>(x, Wqkv, bqkv, Wsq, bsq);
    pool_kernel  <<<BB*NHH, 256>>>();
    conv_kernel  <<<(2*NHH*NN)/256, 256>>>(Wdw, bdw);
    table_kernel <<<dim3(63, NHH), 256>>>();
    rowmax_kernel<<<NHH, 256>>>();
    flash_mma    <<<dim3(NN/128, BB*NHH), 256, SMEM_BYTES>>>();
    proj_kernel  <<<NROWS/64, 256>>>(Wproj, bproj, out);
}